// round 1
// baseline (speedup 1.0000x reference)
#include <cuda_runtime.h>

#define N_NODES 100000
#define N_EDGES 1600000
#define HID 64
#define SCAN_T 512
#define SCAN_NB ((N_NODES + SCAN_T - 1) / SCAN_T)   // 196

// ---------------- scratch (device globals; no runtime allocation) ----------------
__device__ float g_hA[N_NODES * HID];
__device__ float g_hB[N_NODES * HID];
__device__ float g_agg[N_NODES * HID];
__device__ int   g_csr[N_EDGES];
__device__ int   g_cnt[N_NODES];
__device__ int   g_off[N_NODES + 1];
__device__ int   g_wp[N_NODES];
__device__ int   g_bsum[SCAN_NB + 1];
__device__ int   g_is64;

// ---------------- edge dtype detection ----------------
// int64 little-endian: high 32-bit word of every entry is 0 (values in [0,100000)).
// int32: odd int32 words are real indices -> essentially never all zero over 64 samples.
__global__ void k_detect(const int* __restrict__ e32) {
    if (threadIdx.x == 0) {
        int is64 = 1;
        for (int i = 0; i < 64; i++)
            if (e32[2 * i + 1] != 0) { is64 = 0; break; }
        g_is64 = is64;
    }
}

__device__ __forceinline__ int edge_at(const void* eptr, long long idx, int is64) {
    if (is64) return (int)((const long long*)eptr)[idx];
    return ((const int*)eptr)[idx];
}

// ---------------- CSR build ----------------
__global__ void k_zero_cnt() {
    int i = blockIdx.x * blockDim.x + threadIdx.x;
    if (i < N_NODES) g_cnt[i] = 0;
}

__global__ void k_hist(const void* __restrict__ eptr) {
    long long e = (long long)blockIdx.x * blockDim.x + threadIdx.x;
    if (e >= N_EDGES) return;
    int is64 = g_is64;
    int d = edge_at(eptr, (long long)N_EDGES + e, is64);
    atomicAdd(&g_cnt[d], 1);
}

__global__ void k_scan1() {
    __shared__ int s[SCAN_T];
    int t = threadIdx.x;
    int i = blockIdx.x * SCAN_T + t;
    int v = (i < N_NODES) ? g_cnt[i] : 0;
    s[t] = v;
    __syncthreads();
    for (int o = 1; o < SCAN_T; o <<= 1) {
        int add = (t >= o) ? s[t - o] : 0;
        __syncthreads();
        s[t] += add;
        __syncthreads();
    }
    if (i < N_NODES) g_off[i] = s[t] - v;   // block-local exclusive
    if (t == SCAN_T - 1) g_bsum[blockIdx.x] = s[t];
}

__global__ void k_scan2(int nblk) {
    if (threadIdx.x == 0) {
        int acc = 0;
        for (int b = 0; b < nblk; b++) {
            int t = g_bsum[b];
            g_bsum[b] = acc;
            acc += t;
        }
        g_off[N_NODES] = acc;   // == N_EDGES
    }
}

__global__ void k_scan3() {
    int i = blockIdx.x * SCAN_T + threadIdx.x;
    if (i < N_NODES) {
        int v = g_off[i] + g_bsum[blockIdx.x];
        g_off[i] = v;
        g_wp[i] = v;
    }
}

__global__ void k_scatter(const void* __restrict__ eptr) {
    long long e = (long long)blockIdx.x * blockDim.x + threadIdx.x;
    if (e >= N_EDGES) return;
    int is64 = g_is64;
    int s = edge_at(eptr, e, is64);
    int d = edge_at(eptr, (long long)N_EDGES + e, is64);
    int pos = atomicAdd(&g_wp[d], 1);
    g_csr[pos] = s;
}

// ---------------- pre-MLP: h = relu(x @ preW.T + preb), x:[N,3], preW:[64,3] ----------------
__global__ void k_pre(const float* __restrict__ x, const float* __restrict__ W,
                      const float* __restrict__ b, float* __restrict__ h) {
    int idx = blockIdx.x * blockDim.x + threadIdx.x;
    if (idx >= N_NODES * HID) return;
    int i = idx >> 6, j = idx & 63;
    float acc = b[j]
              + x[i * 3 + 0] * W[j * 3 + 0]
              + x[i * 3 + 1] * W[j * 3 + 1]
              + x[i * 3 + 2] * W[j * 3 + 2];
    h[idx] = fmaxf(acc, 0.0f);
}

// ---------------- aggregation: agg[i] = sum_{e in CSR(i)} h[src(e)] ----------------
// one warp per node; each lane owns a float2 (2 columns) -> full 256B row per edge, one request
__global__ void __launch_bounds__(256) k_agg(const float* __restrict__ h) {
    int gtid = blockIdx.x * blockDim.x + threadIdx.x;
    int node = gtid >> 5;
    int lane = gtid & 31;
    if (node >= N_NODES) return;
    int s = g_off[node], e = g_off[node + 1];
    const float2* __restrict__ h2 = (const float2*)h;
    float2 acc = make_float2(0.f, 0.f);
    for (int k = s; k < e; k++) {
        int src = g_csr[k];
        float2 v = __ldg(&h2[src * 32 + lane]);
        acc.x += v.x;
        acc.y += v.y;
    }
    ((float2*)g_agg)[node * 32 + lane] = acc;
}

// ---------------- transform: hout = relu(agg@relW.T + hin@rootW.T + relb) ----------------
// combined K=128 GEMM: A=[agg|hin] (128 nodes x 128), Wc[k][j]=relW[j][k] (k<64) else rootW[j][k-64]
#define XF_SMEM ((128 * 64 + 128 * 129) * 4)   // 98816 bytes
__global__ void __launch_bounds__(256, 2) k_xform(
        const float* __restrict__ hin,
        const float* __restrict__ relW, const float* __restrict__ relb,
        const float* __restrict__ rootW,
        float* __restrict__ hout) {
    extern __shared__ float smem[];
    float* sW = smem;              // [128][64]
    float* sA = smem + 128 * 64;   // [128][129] padded
    int tid = threadIdx.x;
    int n0 = blockIdx.x * 128;

    // load combined weights (k-major)
    for (int f = tid; f < 128 * 64; f += 256) {
        int k = f >> 6, j = f & 63;
        sW[f] = (k < 64) ? relW[j * 64 + k] : rootW[j * 64 + (k - 64)];
    }
    // load A tile: 128 nodes x 128 k (float4 granularity)
    for (int f = tid; f < 128 * 32; f += 256) {
        int m = f >> 5, q = f & 31;
        int n = n0 + m;
        int k = q * 4;
        float4 v;
        if (n < N_NODES) {
            const float* src = (k < 64) ? &g_agg[n * 64 + k] : &hin[n * 64 + (k - 64)];
            v = *(const float4*)src;
        } else {
            v = make_float4(0.f, 0.f, 0.f, 0.f);
        }
        float* dst = &sA[m * 129 + k];
        dst[0] = v.x; dst[1] = v.y; dst[2] = v.z; dst[3] = v.w;
    }
    __syncthreads();

    int c = tid & 15;    // col group: cols 4c..4c+3
    int r = tid >> 4;    // row group: rows 8r..8r+7
    float acc[8][4];
#pragma unroll
    for (int i = 0; i < 8; i++)
#pragma unroll
        for (int j = 0; j < 4; j++) acc[i][j] = 0.f;

#pragma unroll 4
    for (int k = 0; k < 128; k++) {
        float4 w = *(const float4*)&sW[k * 64 + c * 4];
#pragma unroll
        for (int i = 0; i < 8; i++) {
            float a = sA[(r * 8 + i) * 129 + k];
            acc[i][0] += a * w.x;
            acc[i][1] += a * w.y;
            acc[i][2] += a * w.z;
            acc[i][3] += a * w.w;
        }
    }

    float4 bb = *(const float4*)&relb[c * 4];
#pragma unroll
    for (int i = 0; i < 8; i++) {
        int n = n0 + r * 8 + i;
        if (n < N_NODES) {
            float4 o;
            o.x = fmaxf(acc[i][0] + bb.x, 0.f);
            o.y = fmaxf(acc[i][1] + bb.y, 0.f);
            o.z = fmaxf(acc[i][2] + bb.z, 0.f);
            o.w = fmaxf(acc[i][3] + bb.w, 0.f);
            *(float4*)&hout[n * 64 + c * 4] = o;
        }
    }
}

// ---------------- post-MLP: out = relu(h @ postW.T + postb), postW:[2,64] ----------------
__global__ void __launch_bounds__(256) k_post(const float* __restrict__ h,
                                              const float* __restrict__ W,
                                              const float* __restrict__ b,
                                              float* __restrict__ out) {
    int gtid = blockIdx.x * blockDim.x + threadIdx.x;
    int node = gtid >> 5;
    int lane = gtid & 31;
    if (node >= N_NODES) return;
    float2 v = ((const float2*)h)[node * 32 + lane];
    float a0 = v.x * W[2 * lane] + v.y * W[2 * lane + 1];
    float a1 = v.x * W[64 + 2 * lane] + v.y * W[64 + 2 * lane + 1];
#pragma unroll
    for (int o = 16; o > 0; o >>= 1) {
        a0 += __shfl_down_sync(0xFFFFFFFFu, a0, o);
        a1 += __shfl_down_sync(0xFFFFFFFFu, a1, o);
    }
    if (lane == 0) {
        out[2 * node + 0] = fmaxf(a0 + b[0], 0.f);
        out[2 * node + 1] = fmaxf(a1 + b[1], 0.f);
    }
}

// ---------------- launch ----------------
extern "C" void kernel_launch(void* const* d_in, const int* in_sizes, int n_in,
                              void* d_out, int out_size) {
    const float* x     = (const float*)d_in[0];
    const void*  ei    = d_in[1];
    const float* preW  = (const float*)d_in[2];
    const float* preb  = (const float*)d_in[3];
    const float* postW = (const float*)d_in[4];
    const float* postb = (const float*)d_in[5];
    const float* relW[3]  = {(const float*)d_in[6],  (const float*)d_in[9],  (const float*)d_in[12]};
    const float* relb[3]  = {(const float*)d_in[7],  (const float*)d_in[10], (const float*)d_in[13]};
    const float* rootW[3] = {(const float*)d_in[8],  (const float*)d_in[11], (const float*)d_in[14]};
    float* out = (float*)d_out;

    cudaFuncSetAttribute(k_xform, cudaFuncAttributeMaxDynamicSharedMemorySize, XF_SMEM);

    float *hA, *hB;
    cudaGetSymbolAddress((void**)&hA, g_hA);
    cudaGetSymbolAddress((void**)&hB, g_hB);

    // CSR build (amortized over 3 layers; all int ops)
    k_detect<<<1, 32>>>((const int*)ei);
    k_zero_cnt<<<(N_NODES + 255) / 256, 256>>>();
    k_hist<<<(N_EDGES + 255) / 256, 256>>>(ei);
    k_scan1<<<SCAN_NB, SCAN_T>>>();
    k_scan2<<<1, 32>>>(SCAN_NB);
    k_scan3<<<SCAN_NB, SCAN_T>>>();
    k_scatter<<<(N_EDGES + 255) / 256, 256>>>(ei);

    // pre-MLP
    k_pre<<<(N_NODES * HID + 255) / 256, 256>>>(x, preW, preb, hA);

    // 3 message-passing layers (ping-pong hA/hB)
    const int agg_blocks = (N_NODES * 32 + 255) / 256;
    const int xf_blocks  = (N_NODES + 127) / 128;
    float* hin = hA;
    float* hout = hB;
    for (int l = 0; l < 3; l++) {
        k_agg<<<agg_blocks, 256>>>(hin);
        k_xform<<<xf_blocks, 256, XF_SMEM>>>(hin, relW[l], relb[l], rootW[l], hout);
        float* t = hin; hin = hout; hout = t;
    }

    // post-MLP (final h is in `hin` after the swap)
    k_post<<<(N_NODES * 32 + 255) / 256, 256>>>(hin, postW, postb, out);
}